// round 2
// baseline (speedup 1.0000x reference)
#include <cuda_runtime.h>
#include <cstdint>
#include <math.h>

#define BB 32
#define LL 64
#define EE 512
#define UU 512
#define VV 32000
#define J4 2048   // 4*UU

// ---------------- device scratch (no allocation allowed) ----------------
__device__ float g_wmask[BB*EE];          // word dropout mask [B,E]
__device__ float g_rmask[4*BB*UU];        // recurrent masks [4,B,U]
__device__ float g_fmask[BB*LL*UU];       // final mask [B,L,U]
__device__ float g_x[LL*BB*EE];           // inputs, time-major [L,B,E]
__device__ float g_zin[LL*BB*J4];         // precomputed input-path z [L,B,4U]
__device__ float g_z[BB*J4];              // per-step z [B,4U]
__device__ float g_c[BB*UU];              // cell state
__device__ float g_hm[4*BB*UU];           // h * rec_mask[g], per gate
__device__ float g_rnn[BB*LL*UU];         // rnn_out*fin_mask, rows = b*L+t
__device__ int   g_is64;                  // targets dtype flag

// ---------------- threefry2x32 (JAX-compatible, 20 rounds) ----------------
__host__ __device__ inline void tf2x32(uint32_t k0, uint32_t k1,
                                       uint32_t x0, uint32_t x1,
                                       uint32_t* o0, uint32_t* o1)
{
    uint32_t ks2 = k0 ^ k1 ^ 0x1BD11BDAu;
    x0 += k0; x1 += k1;
#define RND(r) { x0 += x1; x1 = (x1 << (r)) | (x1 >> (32 - (r))); x1 ^= x0; }
    RND(13) RND(15) RND(26) RND(6)  x0 += k1;  x1 += ks2 + 1u;
    RND(17) RND(29) RND(16) RND(24) x0 += ks2; x1 += k0  + 2u;
    RND(13) RND(15) RND(26) RND(6)  x0 += k0;  x1 += k1  + 3u;
    RND(17) RND(29) RND(16) RND(24) x0 += k1;  x1 += ks2 + 4u;
    RND(13) RND(15) RND(26) RND(6)  x0 += ks2; x1 += k0  + 5u;
#undef RND
    *o0 = x0; *o1 = x1;
}

__device__ inline float bern_mask(uint32_t bits)
{
    // jax.random.uniform: bitcast((bits>>9)|0x3f800000) - 1.0 ; bernoulli: u < p
    float u = __uint_as_float((bits >> 9) | 0x3f800000u) - 1.0f;
    return (u < 0.7f) ? (1.0f / 0.7f) : 0.0f;
}

// PARTITIONABLE threefry random_bits (modern JAX default):
// element i -> threefry2x32(key, hi=0, lo=i); 32-bit output = o0 ^ o1.
__global__ void mask_kernel(uint32_t k0, uint32_t k1, int n, float* out)
{
    int i = blockIdx.x * blockDim.x + threadIdx.x;
    if (i >= n) return;
    uint32_t o0, o1;
    tf2x32(k0, k1, 0u, (uint32_t)i, &o0, &o1);
    out[i] = bern_mask(o0 ^ o1);
}

// ---------------- targets dtype detection ----------------
__global__ void detect_kernel(const unsigned int* tw)
{
    __shared__ int flag;
    if (threadIdx.x == 0) flag = 1;
    __syncthreads();
    // If int64: high words (odd 32-bit words) of first 1024 values are all 0.
    // If int32: those words are random tokens in [0,32000) -> essentially never all 0.
    for (int i = threadIdx.x; i < 1024; i += 256)
        if (tw[2*i + 1] != 0u) atomicAnd(&flag, 0);
    __syncthreads();
    if (threadIdx.x == 0) g_is64 = flag;
}

// ---------------- build X: image step + embedded words * word dropout ----------------
__global__ void embed_kernel(const float* __restrict__ images,
                             const void*  __restrict__ targs,
                             const float* __restrict__ emb)
{
    int idx = blockIdx.x * blockDim.x + threadIdx.x;   // [L*B*E)
    int t = idx >> 14;            // / (B*E) = /16384
    int r = idx & 16383;
    int b = r >> 9;
    int e = r & 511;
    float val;
    if (t == 0) {
        val = images[b * EE + e];
    } else {
        int ti = b * LL + (t - 1);
        int tok = g_is64 ? (int)(((const long long*)targs)[ti])
                         : ((const int*)targs)[ti];
        val = emb[tok * EE + e] * g_wmask[b * EE + e];
    }
    g_x[idx] = val;
}

__global__ void init_kernel()
{
    int i = blockIdx.x * blockDim.x + threadIdx.x;
    if (i < BB*UU) g_c[i] = 0.0f;
    if (i < 4*BB*UU) g_hm[i] = 0.0f;
}

// ---------------- generic fp32 SGEMM: C[M,N] = A[M,K] @ B[K,N] + bias[N] ----------------
// BM=BN=128, BK=8, 256 threads, 8x8 per-thread tile. All dims divisible.
__global__ __launch_bounds__(256) void sgemm128(const float* __restrict__ A,
                                                const float* __restrict__ Bm,
                                                const float* __restrict__ bias,
                                                float* __restrict__ C,
                                                int M, int N, int K)
{
    __shared__ float Ast[8][128];
    __shared__ float Bs[8][128];
    int tid = threadIdx.x;
    int bm0 = blockIdx.y * 128, bn0 = blockIdx.x * 128;
    int tx = tid & 15, ty = tid >> 4;

    float acc[8][8];
#pragma unroll
    for (int i = 0; i < 8; i++)
#pragma unroll
        for (int j = 0; j < 8; j++) acc[i][j] = 0.0f;

    int arow = tid >> 1, ak = (tid & 1) * 4;     // A tile: 128 rows x 8 k
    int bkr = tid >> 5, bc = (tid & 31) * 4;     // B tile: 8 k x 128 cols

    for (int k0 = 0; k0 < K; k0 += 8) {
        float4 av = *(const float4*)&A[(size_t)(bm0 + arow) * K + k0 + ak];
        Ast[ak + 0][arow] = av.x; Ast[ak + 1][arow] = av.y;
        Ast[ak + 2][arow] = av.z; Ast[ak + 3][arow] = av.w;
        float4 bv = *(const float4*)&Bm[(size_t)(k0 + bkr) * N + bn0 + bc];
        *(float4*)&Bs[bkr][bc] = bv;
        __syncthreads();
#pragma unroll
        for (int kk = 0; kk < 8; kk++) {
            float a[8], b[8];
#pragma unroll
            for (int i = 0; i < 8; i++) a[i] = Ast[kk][ty * 8 + i];
#pragma unroll
            for (int j = 0; j < 8; j++) b[j] = Bs[kk][tx * 8 + j];
#pragma unroll
            for (int i = 0; i < 8; i++)
#pragma unroll
                for (int j = 0; j < 8; j++) acc[i][j] += a[i] * b[j];
        }
        __syncthreads();
    }
#pragma unroll
    for (int i = 0; i < 8; i++) {
        int row = bm0 + ty * 8 + i;
#pragma unroll
        for (int j = 0; j < 8; j++) {
            int col = bn0 + tx * 8 + j;
            C[(size_t)row * N + col] = acc[i][j] + bias[col];
        }
    }
}

// ---------------- per-step recurrent GEMM: z = zin[t] + (h*mask_g) @ Wrec_g ----------------
// grid 64 blocks: g = bx/16 (gate), ct = bx%16 (32-col tile). 256 threads.
__global__ __launch_bounds__(256) void lstm_zrec(const float* __restrict__ Wrec, int t)
{
    int g  = blockIdx.x >> 4;
    int ct = blockIdx.x & 15;
    int j0 = g * 512 + ct * 32;
    int tid = threadIdx.x;
    int c  = tid & 31;        // column in tile
    int bq = tid >> 5;        // 0..7
    int b0 = bq * 4;          // 4 batches per thread

    __shared__ float sH[64][36];   // hm chunk, transposed [k][b], padded
    __shared__ float sW[64][32];   // Wrec chunk [k][c]

    float acc[4];
#pragma unroll
    for (int i = 0; i < 4; i++)
        acc[i] = g_zin[t * (BB*J4) + (b0 + i) * J4 + j0 + c];

    const float* hmg = &g_hm[g * (BB*UU)];
    for (int k0 = 0; k0 < UU; k0 += 64) {
        for (int idx = tid; idx < 2048; idx += 256) {
            int b = idx >> 6, k = idx & 63;
            sH[k][b] = hmg[b * UU + k0 + k];
        }
        for (int idx = tid; idx < 2048; idx += 256) {
            int k = idx >> 5, cc = idx & 31;
            sW[k][cc] = Wrec[(size_t)(k0 + k) * J4 + j0 + cc];
        }
        __syncthreads();
#pragma unroll
        for (int k = 0; k < 64; k++) {
            float w = sW[k][c];
            float4 h4 = *(const float4*)&sH[k][b0];
            acc[0] += w * h4.x;
            acc[1] += w * h4.y;
            acc[2] += w * h4.z;
            acc[3] += w * h4.w;
        }
        __syncthreads();
    }
#pragma unroll
    for (int i = 0; i < 4; i++)
        g_z[(b0 + i) * J4 + j0 + c] = acc[i];
}

// ---------------- gate nonlinearity + state update + mask products ----------------
__global__ void lstm_gate(int t)
{
    int idx = blockIdx.x * blockDim.x + threadIdx.x;   // [B*U)
    int b = idx >> 9;
    int u = idx & 511;
    float zi = g_z[b * J4 + u];
    float zf = g_z[b * J4 + 512 + u];
    float zg = g_z[b * J4 + 1024 + u];
    float zo = g_z[b * J4 + 1536 + u];
    float ig = 1.0f / (1.0f + expf(-zi));
    float fg = 1.0f / (1.0f + expf(-zf));
    float gg = tanhf(zg);
    float og = 1.0f / (1.0f + expf(-zo));
    float c  = fg * g_c[idx] + ig * gg;
    g_c[idx] = c;
    float h  = og * tanhf(c);
#pragma unroll
    for (int g = 0; g < 4; g++)
        g_hm[g * (BB*UU) + idx] = h * g_rmask[g * (BB*UU) + idx];
    int row = b * LL + t;
    g_rnn[row * UU + u] = h * g_fmask[row * UU + u];
}

// ---------------- launch ----------------
extern "C" void kernel_launch(void* const* d_in, const int* in_sizes, int n_in,
                              void* d_out, int out_size)
{
    const float* images = (const float*)d_in[1];
    const void*  targs  =                d_in[2];
    const float* emb    = (const float*)d_in[3];
    const float* W_in   = (const float*)d_in[4];
    const float* W_rec  = (const float*)d_in[5];
    const float* b_lstm = (const float*)d_in[6];
    const float* W_out  = (const float*)d_in[7];
    const float* b_out  = (const float*)d_in[8];
    float* out = (float*)d_out;

    // PARTITIONABLE (fold-like) split of key(42) = (0,42):
    // subkey i = full 2x32 output of threefry((0,42), (0, i))
    uint32_t k1a,k1b, k2a,k2b, k3a,k3b;
    tf2x32(0u, 42u, 0u, 0u, &k1a, &k1b);
    tf2x32(0u, 42u, 0u, 1u, &k2a, &k2b);
    tf2x32(0u, 42u, 0u, 2u, &k3a, &k3b);

    float *p_wmask, *p_rmask, *p_fmask, *p_x, *p_zin, *p_rnn;
    cudaGetSymbolAddress((void**)&p_wmask, g_wmask);
    cudaGetSymbolAddress((void**)&p_rmask, g_rmask);
    cudaGetSymbolAddress((void**)&p_fmask, g_fmask);
    cudaGetSymbolAddress((void**)&p_x,     g_x);
    cudaGetSymbolAddress((void**)&p_zin,   g_zin);
    cudaGetSymbolAddress((void**)&p_rnn,   g_rnn);

    detect_kernel<<<1, 256>>>((const unsigned int*)targs);

    mask_kernel<<<(BB*EE)    / 256, 256>>>(k1a, k1b, BB*EE,    p_wmask);
    mask_kernel<<<(4*BB*UU)  / 256, 256>>>(k2a, k2b, 4*BB*UU,  p_rmask);
    mask_kernel<<<(BB*LL*UU) / 256, 256>>>(k3a, k3b, BB*LL*UU, p_fmask);

    embed_kernel<<<(LL*BB*EE) / 256, 256>>>(images, targs, emb);
    init_kernel<<<(4*BB*UU) / 256, 256>>>();

    // Z_in for all timesteps: [L*B, 4U] = X[L*B, E] @ W_in[E, 4U] + b_lstm
    sgemm128<<<dim3(J4/128, (LL*BB)/128), 256>>>(p_x, W_in, b_lstm, p_zin, LL*BB, J4, EE);

    for (int t = 0; t < LL; t++) {
        lstm_zrec<<<64, 256>>>(W_rec, t);
        lstm_gate<<<64, 256>>>(t);
    }

    // predictions: [B*L, V] = rnn_out[B*L, U] @ W_out[U, V] + b_out
    sgemm128<<<dim3(VV/128, (BB*LL)/128), 256>>>(p_rnn, W_out, b_out, out, BB*LL, VV, UU);
}

// round 3
// speedup vs baseline: 1.4669x; 1.4669x over previous
#include <cuda_runtime.h>
#include <cstdint>
#include <math.h>

#define BB 32
#define LL 64
#define EE 512
#define UU 512
#define VV 32000
#define J4 2048   // 4*UU

// ---------------- device scratch (no allocation allowed) ----------------
__device__ float g_wmask[BB*EE];          // word dropout mask [B,E]
__device__ float g_rmask[4*BB*UU];        // recurrent masks [4,B,U]
__device__ float g_fmask[BB*LL*UU];       // final mask [B,L,U]
__device__ float g_x[LL*BB*EE];           // inputs, time-major [L,B,E]
__device__ float g_zin[LL*BB*J4];         // precomputed input-path z [L,B,4U]
__device__ float g_z[BB*J4];              // per-step z [B,4U]
__device__ float g_c[BB*UU];              // cell state
__device__ float g_hm[4*BB*UU];           // h * rec_mask[g], per gate
__device__ float g_rnn[BB*LL*UU];         // rnn_out*fin_mask, rows = b*L+t
__device__ int   g_is64;                  // targets dtype flag

// ---------------- threefry2x32 (JAX-compatible, 20 rounds) ----------------
__host__ __device__ inline void tf2x32(uint32_t k0, uint32_t k1,
                                       uint32_t x0, uint32_t x1,
                                       uint32_t* o0, uint32_t* o1)
{
    uint32_t ks2 = k0 ^ k1 ^ 0x1BD11BDAu;
    x0 += k0; x1 += k1;
#define RND(r) { x0 += x1; x1 = (x1 << (r)) | (x1 >> (32 - (r))); x1 ^= x0; }
    RND(13) RND(15) RND(26) RND(6)  x0 += k1;  x1 += ks2 + 1u;
    RND(17) RND(29) RND(16) RND(24) x0 += ks2; x1 += k0  + 2u;
    RND(13) RND(15) RND(26) RND(6)  x0 += k0;  x1 += k1  + 3u;
    RND(17) RND(29) RND(16) RND(24) x0 += k1;  x1 += ks2 + 4u;
    RND(13) RND(15) RND(26) RND(6)  x0 += ks2; x1 += k0  + 5u;
#undef RND
    *o0 = x0; *o1 = x1;
}

__device__ inline float bern_mask(uint32_t bits)
{
    float u = __uint_as_float((bits >> 9) | 0x3f800000u) - 1.0f;
    return (u < 0.7f) ? (1.0f / 0.7f) : 0.0f;
}

// PARTITIONABLE threefry random_bits: element i -> threefry(key, (0,i)); bits = o0^o1
__global__ void mask_kernel(uint32_t k0, uint32_t k1, int n, float* out)
{
    int i = blockIdx.x * blockDim.x + threadIdx.x;
    if (i >= n) return;
    uint32_t o0, o1;
    tf2x32(k0, k1, 0u, (uint32_t)i, &o0, &o1);
    out[i] = bern_mask(o0 ^ o1);
}

// ---------------- targets dtype detection ----------------
__global__ void detect_kernel(const unsigned int* tw)
{
    __shared__ int flag;
    if (threadIdx.x == 0) flag = 1;
    __syncthreads();
    for (int i = threadIdx.x; i < 1024; i += 256)
        if (tw[2*i + 1] != 0u) atomicAnd(&flag, 0);
    __syncthreads();
    if (threadIdx.x == 0) g_is64 = flag;
}

// ---------------- build X: image step + embedded words * word dropout ----------------
__global__ void embed_kernel(const float* __restrict__ images,
                             const void*  __restrict__ targs,
                             const float* __restrict__ emb)
{
    int idx = blockIdx.x * blockDim.x + threadIdx.x;   // [L*B*E)
    int t = idx >> 14;
    int r = idx & 16383;
    int b = r >> 9;
    int e = r & 511;
    float val;
    if (t == 0) {
        val = images[b * EE + e];
    } else {
        int ti = b * LL + (t - 1);
        int tok = g_is64 ? (int)(((const long long*)targs)[ti])
                         : ((const int*)targs)[ti];
        val = emb[tok * EE + e] * g_wmask[b * EE + e];
    }
    g_x[idx] = val;
}

__global__ void init_kernel()
{
    int i = blockIdx.x * blockDim.x + threadIdx.x;
    if (i < BB*UU) g_c[i] = 0.0f;
    if (i < 4*BB*UU) g_hm[i] = 0.0f;
}

// ---------------- fp32 SGEMM (kept for zin; full precision feeds recurrence) ----------------
__global__ __launch_bounds__(256) void sgemm128(const float* __restrict__ A,
                                                const float* __restrict__ Bm,
                                                const float* __restrict__ bias,
                                                float* __restrict__ C,
                                                int M, int N, int K)
{
    __shared__ float Ast[8][128];
    __shared__ float Bs[8][128];
    int tid = threadIdx.x;
    int bm0 = blockIdx.y * 128, bn0 = blockIdx.x * 128;
    int tx = tid & 15, ty = tid >> 4;

    float acc[8][8];
#pragma unroll
    for (int i = 0; i < 8; i++)
#pragma unroll
        for (int j = 0; j < 8; j++) acc[i][j] = 0.0f;

    int arow = tid >> 1, ak = (tid & 1) * 4;
    int bkr = tid >> 5, bc = (tid & 31) * 4;

    for (int k0 = 0; k0 < K; k0 += 8) {
        float4 av = *(const float4*)&A[(size_t)(bm0 + arow) * K + k0 + ak];
        Ast[ak + 0][arow] = av.x; Ast[ak + 1][arow] = av.y;
        Ast[ak + 2][arow] = av.z; Ast[ak + 3][arow] = av.w;
        float4 bv = *(const float4*)&Bm[(size_t)(k0 + bkr) * N + bn0 + bc];
        *(float4*)&Bs[bkr][bc] = bv;
        __syncthreads();
#pragma unroll
        for (int kk = 0; kk < 8; kk++) {
            float a[8], b[8];
#pragma unroll
            for (int i = 0; i < 8; i++) a[i] = Ast[kk][ty * 8 + i];
#pragma unroll
            for (int j = 0; j < 8; j++) b[j] = Bs[kk][tx * 8 + j];
#pragma unroll
            for (int i = 0; i < 8; i++)
#pragma unroll
                for (int j = 0; j < 8; j++) acc[i][j] += a[i] * b[j];
        }
        __syncthreads();
    }
#pragma unroll
    for (int i = 0; i < 8; i++) {
        int row = bm0 + ty * 8 + i;
#pragma unroll
        for (int j = 0; j < 8; j++) {
            int col = bn0 + tx * 8 + j;
            C[(size_t)row * N + col] = acc[i][j] + bias[col];
        }
    }
}

// ---------------- tf32 tensor-core GEMM: C[M,N] = A[M,K]@B[K,N] + bias ----------------
// 128x128x16 CTA tile, 8 warps (2m x 4n), warp tile 64x32, mma.m16n8k8.tf32.
__device__ inline uint32_t f2tf32(float x)
{
    uint32_t r;
    asm("cvt.rna.tf32.f32 %0, %1;" : "=r"(r) : "f"(x));
    return r;
}

__global__ __launch_bounds__(256) void tgemm_tf32(const float* __restrict__ A,
                                                  const float* __restrict__ Bm,
                                                  const float* __restrict__ bias,
                                                  float* __restrict__ C,
                                                  int M, int N, int K)
{
    __shared__ float As[2][128][20];   // [row][k], pad 16->20: conflict-free frag reads
    __shared__ float Bs[2][16][132];   // [k][col], pad 128->132

    int tid  = threadIdx.x;
    int lane = tid & 31, wid = tid >> 5;
    int wm0 = (wid >> 2) * 64;
    int wn0 = (wid & 3) * 32;
    int bm = blockIdx.y * 128, bn = blockIdx.x * 128;
    int t4 = lane >> 2, tq = lane & 3;

    // global-load slots
    int arow = tid >> 1, ac = (tid & 1) * 4;      // A: float4 at (arow, ac) and (arow, ac+8)
    int brow = tid >> 4, bc = (tid & 15) * 8;     // B: float4 at (brow, bc) and (brow, bc+4)

    const float* Abase = A + (size_t)(bm + arow) * K + ac;
    const float* Bbase = Bm + (size_t)brow * N + bn + bc;

    float4 av0, av1, bv0, bv1;

    float acc[4][4][4];
#pragma unroll
    for (int i = 0; i < 4; i++)
#pragma unroll
        for (int j = 0; j < 4; j++)
#pragma unroll
            for (int k = 0; k < 4; k++) acc[i][j][k] = 0.0f;

    // prologue: tile 0
    av0 = *(const float4*)(Abase);
    av1 = *(const float4*)(Abase + 8);
    bv0 = *(const float4*)(Bbase);
    bv1 = *(const float4*)(Bbase + 4);
    *(float4*)&As[0][arow][ac]     = av0;
    *(float4*)&As[0][arow][ac + 8] = av1;
    *(float4*)&Bs[0][brow][bc]     = bv0;
    *(float4*)&Bs[0][brow][bc + 4] = bv1;
    __syncthreads();

    int nt = K / 16;
    for (int kt = 0; kt < nt; kt++) {
        int cur = kt & 1;
        if (kt + 1 < nt) {
            const float* ap = Abase + (kt + 1) * 16;
            const float* bp = Bbase + (size_t)(kt + 1) * 16 * N;
            av0 = *(const float4*)(ap);
            av1 = *(const float4*)(ap + 8);
            bv0 = *(const float4*)(bp);
            bv1 = *(const float4*)(bp + 4);
        }
#pragma unroll
        for (int kk = 0; kk < 16; kk += 8) {
            uint32_t af[4][4], bf[4][2];
#pragma unroll
            for (int mi = 0; mi < 4; mi++) {
                int r = wm0 + mi * 16 + t4;
                af[mi][0] = f2tf32(As[cur][r    ][kk + tq]);
                af[mi][1] = f2tf32(As[cur][r + 8][kk + tq]);
                af[mi][2] = f2tf32(As[cur][r    ][kk + 4 + tq]);
                af[mi][3] = f2tf32(As[cur][r + 8][kk + 4 + tq]);
            }
#pragma unroll
            for (int nj = 0; nj < 4; nj++) {
                int ccol = wn0 + nj * 8 + t4;
                bf[nj][0] = f2tf32(Bs[cur][kk + tq][ccol]);
                bf[nj][1] = f2tf32(Bs[cur][kk + 4 + tq][ccol]);
            }
#pragma unroll
            for (int mi = 0; mi < 4; mi++)
#pragma unroll
                for (int nj = 0; nj < 4; nj++) {
                    asm volatile(
                        "mma.sync.aligned.m16n8k8.row.col.f32.tf32.tf32.f32 "
                        "{%0,%1,%2,%3}, {%4,%5,%6,%7}, {%8,%9}, {%0,%1,%2,%3};"
                        : "+f"(acc[mi][nj][0]), "+f"(acc[mi][nj][1]),
                          "+f"(acc[mi][nj][2]), "+f"(acc[mi][nj][3])
                        : "r"(af[mi][0]), "r"(af[mi][1]), "r"(af[mi][2]), "r"(af[mi][3]),
                          "r"(bf[nj][0]), "r"(bf[nj][1]));
                }
        }
        if (kt + 1 < nt) {
            __syncthreads();
            int nxt = (kt + 1) & 1;
            *(float4*)&As[nxt][arow][ac]     = av0;
            *(float4*)&As[nxt][arow][ac + 8] = av1;
            *(float4*)&Bs[nxt][brow][bc]     = bv0;
            *(float4*)&Bs[nxt][brow][bc + 4] = bv1;
            __syncthreads();
        }
    }

    // epilogue: C = acc + bias
#pragma unroll
    for (int mi = 0; mi < 4; mi++) {
        int r0 = bm + wm0 + mi * 16 + t4;
#pragma unroll
        for (int nj = 0; nj < 4; nj++) {
            int col = bn + wn0 + nj * 8 + tq * 2;
            float b0 = bias[col], b1 = bias[col + 1];
            float2 v0 = make_float2(acc[mi][nj][0] + b0, acc[mi][nj][1] + b1);
            float2 v1 = make_float2(acc[mi][nj][2] + b0, acc[mi][nj][3] + b1);
            *(float2*)&C[(size_t)r0 * N + col]       = v0;
            *(float2*)&C[(size_t)(r0 + 8) * N + col] = v1;
        }
    }
}

// ---------------- per-step recurrent GEMM ----------------
__global__ __launch_bounds__(256) void lstm_zrec(const float* __restrict__ Wrec, int t)
{
    int g  = blockIdx.x >> 4;
    int ct = blockIdx.x & 15;
    int j0 = g * 512 + ct * 32;
    int tid = threadIdx.x;
    int c  = tid & 31;
    int bq = tid >> 5;
    int b0 = bq * 4;

    __shared__ float sH[64][36];
    __shared__ float sW[64][32];

    float acc[4];
#pragma unroll
    for (int i = 0; i < 4; i++)
        acc[i] = g_zin[t * (BB*J4) + (b0 + i) * J4 + j0 + c];

    const float* hmg = &g_hm[g * (BB*UU)];
    for (int k0 = 0; k0 < UU; k0 += 64) {
        for (int idx = tid; idx < 2048; idx += 256) {
            int b = idx >> 6, k = idx & 63;
            sH[k][b] = hmg[b * UU + k0 + k];
        }
        for (int idx = tid; idx < 2048; idx += 256) {
            int k = idx >> 5, cc = idx & 31;
            sW[k][cc] = Wrec[(size_t)(k0 + k) * J4 + j0 + cc];
        }
        __syncthreads();
#pragma unroll
        for (int k = 0; k < 64; k++) {
            float w = sW[k][c];
            float4 h4 = *(const float4*)&sH[k][b0];
            acc[0] += w * h4.x;
            acc[1] += w * h4.y;
            acc[2] += w * h4.z;
            acc[3] += w * h4.w;
        }
        __syncthreads();
    }
#pragma unroll
    for (int i = 0; i < 4; i++)
        g_z[(b0 + i) * J4 + j0 + c] = acc[i];
}

// ---------------- gate nonlinearity + state update ----------------
__global__ void lstm_gate(int t)
{
    int idx = blockIdx.x * blockDim.x + threadIdx.x;
    int b = idx >> 9;
    int u = idx & 511;
    float zi = g_z[b * J4 + u];
    float zf = g_z[b * J4 + 512 + u];
    float zg = g_z[b * J4 + 1024 + u];
    float zo = g_z[b * J4 + 1536 + u];
    float ig = 1.0f / (1.0f + expf(-zi));
    float fg = 1.0f / (1.0f + expf(-zf));
    float gg = tanhf(zg);
    float og = 1.0f / (1.0f + expf(-zo));
    float c  = fg * g_c[idx] + ig * gg;
    g_c[idx] = c;
    float h  = og * tanhf(c);
#pragma unroll
    for (int g = 0; g < 4; g++)
        g_hm[g * (BB*UU) + idx] = h * g_rmask[g * (BB*UU) + idx];
    int row = b * LL + t;
    g_rnn[row * UU + u] = h * g_fmask[row * UU + u];
}

// ---------------- launch ----------------
extern "C" void kernel_launch(void* const* d_in, const int* in_sizes, int n_in,
                              void* d_out, int out_size)
{
    const float* images = (const float*)d_in[1];
    const void*  targs  =                d_in[2];
    const float* emb    = (const float*)d_in[3];
    const float* W_in   = (const float*)d_in[4];
    const float* W_rec  = (const float*)d_in[5];
    const float* b_lstm = (const float*)d_in[6];
    const float* W_out  = (const float*)d_in[7];
    const float* b_out  = (const float*)d_in[8];
    float* out = (float*)d_out;

    uint32_t k1a,k1b, k2a,k2b, k3a,k3b;
    tf2x32(0u, 42u, 0u, 0u, &k1a, &k1b);
    tf2x32(0u, 42u, 0u, 1u, &k2a, &k2b);
    tf2x32(0u, 42u, 0u, 2u, &k3a, &k3b);

    float *p_wmask, *p_rmask, *p_fmask, *p_x, *p_zin, *p_rnn;
    cudaGetSymbolAddress((void**)&p_wmask, g_wmask);
    cudaGetSymbolAddress((void**)&p_rmask, g_rmask);
    cudaGetSymbolAddress((void**)&p_fmask, g_fmask);
    cudaGetSymbolAddress((void**)&p_x,     g_x);
    cudaGetSymbolAddress((void**)&p_zin,   g_zin);
    cudaGetSymbolAddress((void**)&p_rnn,   g_rnn);

    detect_kernel<<<1, 256>>>((const unsigned int*)targs);

    mask_kernel<<<(BB*EE)    / 256, 256>>>(k1a, k1b, BB*EE,    p_wmask);
    mask_kernel<<<(4*BB*UU)  / 256, 256>>>(k2a, k2b, 4*BB*UU,  p_rmask);
    mask_kernel<<<(BB*LL*UU) / 256, 256>>>(k3a, k3b, BB*LL*UU, p_fmask);

    embed_kernel<<<(LL*BB*EE) / 256, 256>>>(images, targs, emb);
    init_kernel<<<(4*BB*UU) / 256, 256>>>();

    sgemm128<<<dim3(J4/128, (LL*BB)/128), 256>>>(p_x, W_in, b_lstm, p_zin, LL*BB, J4, EE);

    for (int t = 0; t < LL; t++) {
        lstm_zrec<<<64, 256>>>(W_rec, t);
        lstm_gate<<<64, 256>>>(t);
    }

    // output projection on tensor cores (tf32)
    tgemm_tf32<<<dim3(VV/128, (BB*LL)/128), 256>>>(p_rnn, W_out, b_out, out, BB*LL, VV, UU);
}